// round 1
// baseline (speedup 1.0000x reference)
#include <cuda_runtime.h>

// Blended MLP via table + linear interpolation.
// f(x) = sum_e B_e(x) * MLP_e(x) is a smooth scalar function of x in [0,1).
// 1) build_partial: per (table-point, expert) exact evaluation -> g_partial
// 2) reduce: sum experts -> g_table (deterministic order)
// 3) interp: stream 4M x values, lerp from smem-resident table

#define TAB   8192
#define NPTS  (TAB + 1)
#define NEXP  7

__device__ float g_partial[NEXP * NPTS];
__device__ float g_table[NPTS];

// Cox-de Boor, degree 3, matching the reference's half-open degree-0 intervals
// and safe-division semantics (uniform knots -> denominators nonzero anyway).
__device__ __forceinline__ float bspline3(float x, const float* kn, int i) {
    float N[4];
#pragma unroll
    for (int j = 0; j < 4; j++)
        N[j] = (kn[i + j] <= x && x < kn[i + j + 1]) ? 1.0f : 0.0f;
#pragma unroll
    for (int d = 1; d <= 3; d++) {
#pragma unroll
        for (int j = 0; j <= 3 - d; j++) {
            float d1 = kn[i + j + d] - kn[i + j];
            float d2 = kn[i + j + d + 1] - kn[i + j + 1];
            float t1 = (d1 != 0.0f) ? (x - kn[i + j]) / d1 * N[j] : 0.0f;
            float t2 = (d2 != 0.0f) ? (kn[i + j + d + 1] - x) / d2 * N[j + 1] : 0.0f;
            N[j] = t1 + t2;
        }
    }
    return N[0];
}

__global__ void build_partial_kernel(const float* __restrict__ knots,
                                     const float* __restrict__ W1, const float* __restrict__ b1,
                                     const float* __restrict__ W2, const float* __restrict__ b2,
                                     const float* __restrict__ W3, const float* __restrict__ b3) {
    __shared__ float sW1[NEXP * 16], sb1[NEXP * 16], sW2[NEXP * 256],
                     sb2[NEXP * 16], sW3[NEXP * 16], sb3[NEXP], skn[16];
    int t = threadIdx.x;
    for (int i = t; i < NEXP * 16; i += blockDim.x) {
        sW1[i] = W1[i]; sb1[i] = b1[i]; sb2[i] = b2[i]; sW3[i] = W3[i];
    }
    for (int i = t; i < NEXP * 256; i += blockDim.x) sW2[i] = W2[i];
    if (t < NEXP) sb3[t] = b3[t];
    if (t < 11)   skn[t] = knots[t];
    __syncthreads();

    int gid = blockIdx.x * blockDim.x + t;
    if (gid >= NEXP * NPTS) return;
    int e = gid / NPTS;           // warps (mostly) share e -> smem broadcasts
    int i = gid - e * NPTS;
    float x = (float)i * (1.0f / (float)TAB);

    float h1[16];
#pragma unroll
    for (int k = 0; k < 16; k++)
        h1[k] = tanhf(fmaf(sW1[e * 16 + k], x, sb1[e * 16 + k]));

    float h2[16];
#pragma unroll
    for (int j = 0; j < 16; j++) {
        float acc = sb2[e * 16 + j];
#pragma unroll
        for (int k = 0; k < 16; k++)
            acc = fmaf(sW2[(e * 16 + j) * 16 + k], h1[k], acc);
        h2[j] = tanhf(acc);
    }

    float y = sb3[e];
#pragma unroll
    for (int k = 0; k < 16; k++)
        y = fmaf(sW3[e * 16 + k], h2[k], y);

    float B = bspline3(x, skn, e);
    g_partial[e * NPTS + i] = y * B;
}

__global__ void reduce_kernel() {
    int i = blockIdx.x * blockDim.x + threadIdx.x;
    if (i >= NPTS) return;
    float s = 0.0f;
#pragma unroll
    for (int e = 0; e < NEXP; e++) s += g_partial[e * NPTS + i];
    g_table[i] = s;
}

__device__ __forceinline__ float lerp_tab(float x, const float* tab) {
    float t = x * (float)TAB;
    int i = (int)t;
    i = max(0, min(i, TAB - 1));
    float fr = t - (float)i;
    float a = tab[i];
    float b = tab[i + 1];
    return fmaf(fr, b - a, a);
}

__global__ void __launch_bounds__(512)
interp_kernel(const float4* __restrict__ x4, float4* __restrict__ o4, int n4,
              const float* __restrict__ xs, float* __restrict__ os, int n) {
    __shared__ float tab[NPTS];   // 32772 B static smem, 4 CTAs/SM at 512 thr
    for (int i = threadIdx.x; i < NPTS; i += blockDim.x) tab[i] = g_table[i];
    __syncthreads();

    int stride = gridDim.x * blockDim.x;
    for (int idx = blockIdx.x * blockDim.x + threadIdx.x; idx < n4; idx += stride) {
        float4 v = x4[idx];
        float4 r;
        r.x = lerp_tab(v.x, tab);
        r.y = lerp_tab(v.y, tab);
        r.z = lerp_tab(v.z, tab);
        r.w = lerp_tab(v.w, tab);
        o4[idx] = r;
    }
    // tail (n not divisible by 4)
    if (blockIdx.x == 0) {
        for (int j = n4 * 4 + threadIdx.x; j < n; j += blockDim.x)
            os[j] = lerp_tab(xs[j], tab);
    }
}

extern "C" void kernel_launch(void* const* d_in, const int* in_sizes, int n_in,
                              void* d_out, int out_size) {
    // metadata order: x, knots, W1, b1, W2, b2, W3, b3
    const float* x     = (const float*)d_in[0];
    const float* knots = (const float*)d_in[1];
    const float* W1    = (const float*)d_in[2];
    const float* b1    = (const float*)d_in[3];
    const float* W2    = (const float*)d_in[4];
    const float* b2    = (const float*)d_in[5];
    const float* W3    = (const float*)d_in[6];
    const float* b3    = (const float*)d_in[7];
    float* out = (float*)d_out;
    int n = out_size;             // [B,1] output, equals in_sizes[0]

    build_partial_kernel<<<(NEXP * NPTS + 255) / 256, 256>>>(knots, W1, b1, W2, b2, W3, b3);
    reduce_kernel<<<(NPTS + 255) / 256, 256>>>();

    int n4 = n >> 2;
    interp_kernel<<<592, 512>>>((const float4*)x, (float4*)out, n4, x, out, n);
}

// round 2
// speedup vs baseline: 1.1325x; 1.1325x over previous
#include <cuda_runtime.h>

// Blended MLP via table + linear interpolation.
// f(x) = sum_e B_e(x) * MLP_e(x) is a smooth scalar function of x in [0,1).
// 1) build_partial: per (table-point, expert) exact evaluation -> g_partial
// 2) reduce: sum experts, emit (f, df) float2 pairs -> g_tab2
// 3) interp: stream 4M x values, single LDS.64 lerp from smem table

#define TAB   2048
#define NPTS  (TAB + 1)
#define NEXP  7

__device__ float  g_partial[NEXP * NPTS];
__device__ float2 g_tab2[NPTS];

// Accurate-enough fast tanh: 1 - 2/(exp(2x)+1).
// __expf (MUFU.EX2) rel err ~2^-21, __fdividef ~2 ulp -> abs err ~1e-7.
// Overflow-safe: x>>0 -> e=inf -> 1; x<<0 -> e=0 -> -1.
__device__ __forceinline__ float fast_tanh(float x) {
    float e = __expf(2.0f * x);
    return 1.0f - __fdividef(2.0f, e + 1.0f);
}

// Cox-de Boor, degree 3, matching the reference's half-open degree-0 intervals
// and safe-division semantics.
__device__ __forceinline__ float bspline3(float x, const float* kn, int i) {
    float N[4];
#pragma unroll
    for (int j = 0; j < 4; j++)
        N[j] = (kn[i + j] <= x && x < kn[i + j + 1]) ? 1.0f : 0.0f;
#pragma unroll
    for (int d = 1; d <= 3; d++) {
#pragma unroll
        for (int j = 0; j <= 3 - d; j++) {
            float d1 = kn[i + j + d] - kn[i + j];
            float d2 = kn[i + j + d + 1] - kn[i + j + 1];
            float t1 = (d1 != 0.0f) ? (x - kn[i + j]) / d1 * N[j] : 0.0f;
            float t2 = (d2 != 0.0f) ? (kn[i + j + d + 1] - x) / d2 * N[j + 1] : 0.0f;
            N[j] = t1 + t2;
        }
    }
    return N[0];
}

__global__ void build_partial_kernel(const float* __restrict__ knots,
                                     const float* __restrict__ W1, const float* __restrict__ b1,
                                     const float* __restrict__ W2, const float* __restrict__ b2,
                                     const float* __restrict__ W3, const float* __restrict__ b3) {
    __shared__ float sW1[NEXP * 16], sb1[NEXP * 16], sW2[NEXP * 256],
                     sb2[NEXP * 16], sW3[NEXP * 16], sb3[NEXP], skn[16];
    int t = threadIdx.x;
    for (int i = t; i < NEXP * 16; i += blockDim.x) {
        sW1[i] = W1[i]; sb1[i] = b1[i]; sb2[i] = b2[i]; sW3[i] = W3[i];
    }
    for (int i = t; i < NEXP * 256; i += blockDim.x) sW2[i] = W2[i];
    if (t < NEXP) sb3[t] = b3[t];
    if (t < 11)   skn[t] = knots[t];
    __syncthreads();

    int gid = blockIdx.x * blockDim.x + t;
    if (gid >= NEXP * NPTS) return;
    int e = gid / NPTS;           // warps (mostly) share e -> smem broadcasts
    int i = gid - e * NPTS;
    float x = (float)i * (1.0f / (float)TAB);

    float h1[16];
#pragma unroll
    for (int k = 0; k < 16; k++)
        h1[k] = fast_tanh(fmaf(sW1[e * 16 + k], x, sb1[e * 16 + k]));

    float h2[16];
#pragma unroll
    for (int j = 0; j < 16; j++) {
        float acc = sb2[e * 16 + j];
#pragma unroll
        for (int k = 0; k < 16; k++)
            acc = fmaf(sW2[(e * 16 + j) * 16 + k], h1[k], acc);
        h2[j] = fast_tanh(acc);
    }

    float y = sb3[e];
#pragma unroll
    for (int k = 0; k < 16; k++)
        y = fmaf(sW3[e * 16 + k], h2[k], y);

    float B = bspline3(x, skn, e);
    g_partial[e * NPTS + i] = y * B;
}

__global__ void reduce_kernel() {
    int i = blockIdx.x * blockDim.x + threadIdx.x;
    if (i >= NPTS) return;
    float s = 0.0f, sn = 0.0f;
    int inext = (i < TAB) ? i + 1 : i;
#pragma unroll
    for (int e = 0; e < NEXP; e++) {
        s  += g_partial[e * NPTS + i];
        sn += g_partial[e * NPTS + inext];
    }
    g_tab2[i] = make_float2(s, sn - s);
}

__device__ __forceinline__ float lerp_tab(float x, const float2* tab) {
    float t = x * (float)TAB;
    int i = (int)t;
    i = max(0, min(i, TAB - 1));
    float fr = t - (float)i;
    float2 p = tab[i];            // single LDS.64
    return fmaf(fr, p.y, p.x);
}

__global__ void __launch_bounds__(512)
interp_kernel(const float4* __restrict__ x4, float4* __restrict__ o4, int n4,
              const float* __restrict__ xs, float* __restrict__ os, int n) {
    __shared__ float2 tab[NPTS];  // 16392 B
    {
        const float2* src = g_tab2;
        for (int i = threadIdx.x; i < NPTS; i += blockDim.x) tab[i] = src[i];
    }
    __syncthreads();

    int stride = gridDim.x * blockDim.x;
    for (int idx = blockIdx.x * blockDim.x + threadIdx.x; idx < n4; idx += stride) {
        float4 v = x4[idx];
        float4 r;
        r.x = lerp_tab(v.x, tab);
        r.y = lerp_tab(v.y, tab);
        r.z = lerp_tab(v.z, tab);
        r.w = lerp_tab(v.w, tab);
        o4[idx] = r;
    }
    // tail (n not divisible by 4)
    if (blockIdx.x == 0) {
        for (int j = n4 * 4 + threadIdx.x; j < n; j += blockDim.x)
            os[j] = lerp_tab(xs[j], tab);
    }
}

extern "C" void kernel_launch(void* const* d_in, const int* in_sizes, int n_in,
                              void* d_out, int out_size) {
    // metadata order: x, knots, W1, b1, W2, b2, W3, b3
    const float* x     = (const float*)d_in[0];
    const float* knots = (const float*)d_in[1];
    const float* W1    = (const float*)d_in[2];
    const float* b1    = (const float*)d_in[3];
    const float* W2    = (const float*)d_in[4];
    const float* b2    = (const float*)d_in[5];
    const float* W3    = (const float*)d_in[6];
    const float* b3    = (const float*)d_in[7];
    float* out = (float*)d_out;
    int n = out_size;             // [B,1] output, equals in_sizes[0]

    build_partial_kernel<<<(NEXP * NPTS + 255) / 256, 256>>>(knots, W1, b1, W2, b2, W3, b3);
    reduce_kernel<<<(NPTS + 255) / 256, 256>>>();

    int n4 = n >> 2;
    interp_kernel<<<592, 512>>>((const float4*)x, (float4*)out, n4, x, out, n);
}